// round 2
// baseline (speedup 1.0000x reference)
#include <cuda_runtime.h>

#define N_    16
#define CIN_  512
#define COUT_ 512
#define STY_  512
#define H_    64
#define W_    64
#define HW_   (H_*W_)

// Scratch (static __device__ arrays — no allocation allowed)
__device__ float g_s[N_*CIN_];            // style modulation s[n][ci]
__device__ float g_xs[N_*CIN_*HW_];       // premultiplied input (128 MiB)
__device__ float g_wsum2[CIN_*COUT_];     // [ci][co] = sum_k weight^2
__device__ float g_demod[N_*COUT_];       // per-(n,co) demodulation

// ---------------------------------------------------------------------------
// 1) s[n][ci] = style[n] . style_w[ci] + style_b[ci]
// ---------------------------------------------------------------------------
__global__ void style_kernel(const float* __restrict__ style,
                             const float* __restrict__ style_w,
                             const float* __restrict__ style_b) {
    __shared__ float ssty[STY_];
    int n = blockIdx.x;
    int ci = threadIdx.x;
    ssty[ci] = style[n*STY_ + ci];
    __syncthreads();
    const float* wr = style_w + ci*STY_;
    float acc = 0.f;
    #pragma unroll 8
    for (int k = 0; k < STY_; k++) acc += ssty[k] * wr[k];
    g_s[n*CIN_ + ci] = acc + style_b[ci];
}

// ---------------------------------------------------------------------------
// 2) x'[n][ci][y][x] = s[n][ci] * x[n][ci][y][x]   (fold modulation into input)
// ---------------------------------------------------------------------------
__global__ void premul_kernel(const float* __restrict__ x) {
    const int total4 = N_*CIN_*HW_/4;
    for (int i = blockIdx.x*blockDim.x + threadIdx.x; i < total4;
         i += gridDim.x*blockDim.x) {
        float4 v = ((const float4*)x)[i];
        float s = g_s[(i*4)/HW_];   // HW_ divisible by 4 -> same s for all 4
        v.x *= s; v.y *= s; v.z *= s; v.w *= s;
        ((float4*)g_xs)[i] = v;
    }
}

// ---------------------------------------------------------------------------
// 3) wsum2[ci][co] = sum_k weight[co][ci][k]^2
// ---------------------------------------------------------------------------
__global__ void wsum2_kernel(const float* __restrict__ weight) {
    int idx = blockIdx.x*blockDim.x + threadIdx.x;     // co*CIN + ci
    if (idx >= COUT_*CIN_) return;
    int co = idx / CIN_, ci = idx % CIN_;
    const float* w = weight + idx*9;
    float a = 0.f;
    #pragma unroll
    for (int k = 0; k < 9; k++) { float v = w[k]; a += v*v; }
    g_wsum2[ci*COUT_ + co] = a;
}

// ---------------------------------------------------------------------------
// 4) demod[n][co] = rsqrt( sum_ci s[n][ci]^2 * wsum2[ci][co] + eps )
// ---------------------------------------------------------------------------
__global__ void demod_kernel() {
    int t = blockIdx.x*blockDim.x + threadIdx.x;       // n*COUT + co
    int n = t / COUT_, co = t % COUT_;
    float acc = 1e-8f;
    #pragma unroll 4
    for (int ci = 0; ci < CIN_; ci++) {
        float s = g_s[n*CIN_ + ci];                    // warp-uniform -> broadcast
        acc += s*s * g_wsum2[ci*COUT_ + co];           // coalesced
    }
    g_demod[t] = rsqrtf(acc);
}

// ---------------------------------------------------------------------------
// 5) Conv 3x3 (shared weight) + demod scale + noise + LeakyReLU(0.2)
//    Block tile: 64 couts x (4 rows x 64 cols) pixels. CI chunk = 8.
//    Thread tile: 8 couts x 8 pixels (rows 0..3, cols {tx, tx+32}).
// ---------------------------------------------------------------------------
__global__ __launch_bounds__(256)
void conv_kernel(const float* __restrict__ weight,
                 const float* __restrict__ noise,
                 const float* __restrict__ noise_w,
                 float* __restrict__ out) {
    __shared__ float sIn[8][6][66];      // [ci][row(-1..+4)][col(-1..+64)]
    __shared__ float sW[8][9][65];       // [ci][k][co], padded to kill conflicts

    const int ht  = blockIdx.x;          // 16 row-tiles of 4
    const int cob = blockIdx.y;          // 8 cout blocks of 64
    const int n   = blockIdx.z;
    const int y0  = ht * 4;
    const int co0 = cob * 64;
    const int tx  = threadIdx.x;         // 0..31 (pixel columns)
    const int ty  = threadIdx.y;         // 0..7  (cout groups)
    const int tid = ty*32 + tx;

    float acc[8][8];
    #pragma unroll
    for (int j = 0; j < 8; j++)
        #pragma unroll
        for (int m = 0; m < 8; m++) acc[j][m] = 0.f;

    for (int ci0 = 0; ci0 < CIN_; ci0 += 8) {
        __syncthreads();   // previous chunk's compute done before overwrite

        // --- load input tile (with halo, zero-padded at borders) ---
        for (int i = tid; i < 8*6*66; i += 256) {
            int ci  = i / (6*66);
            int rem = i % (6*66);
            int rr  = rem / 66, cc = rem % 66;
            int gy = y0 + rr - 1, gx = cc - 1;
            float v = 0.f;
            if (gy >= 0 && gy < H_ && gx >= 0 && gx < W_)
                v = g_xs[((n*CIN_ + ci0 + ci)*H_ + gy)*W_ + gx];
            sIn[ci][rr][cc] = v;
        }
        // --- load weights: i -> (co, ci, k); contiguous global reads per co ---
        for (int i = tid; i < 64*8*9; i += 256) {
            int co  = i / 72;
            int rem = i % 72;
            int ci  = rem / 9, k = rem % 9;
            sW[ci][k][co] = weight[((size_t)(co0 + co)*CIN_ + ci0 + ci)*9 + k];
        }
        __syncthreads();

        #pragma unroll
        for (int ci = 0; ci < 8; ci++) {
            #pragma unroll
            for (int kh = 0; kh < 3; kh++) {
                #pragma unroll
                for (int kw = 0; kw < 3; kw++) {
                    float wv[8], iv[8];
                    #pragma unroll
                    for (int j = 0; j < 8; j++)
                        wv[j] = sW[ci][kh*3 + kw][ty + 8*j];   // broadcast
                    #pragma unroll
                    for (int m = 0; m < 8; m++) {
                        int r = m >> 1;
                        int c = tx + 32*(m & 1);
                        iv[m] = sIn[ci][r + kh][c + kw];       // stride-1
                    }
                    #pragma unroll
                    for (int j = 0; j < 8; j++)
                        #pragma unroll
                        for (int m = 0; m < 8; m++)
                            acc[j][m] += wv[j]*iv[m];
                }
            }
        }
    }

    // --- epilogue: demod scale, noise injection, LeakyReLU(0.2) ---
    const float nw = noise_w[0];
    #pragma unroll
    for (int j = 0; j < 8; j++) {
        int co = co0 + ty + 8*j;
        float dm = g_demod[n*COUT_ + co];
        #pragma unroll
        for (int m = 0; m < 8; m++) {
            int r = m >> 1;
            int c = tx + 32*(m & 1);
            int y = y0 + r;
            float v = acc[j][m] * dm;
            v += nw * noise[(n*H_ + y)*W_ + c];
            v = (v >= 0.f) ? v : 0.2f*v;
            out[(((size_t)n*COUT_ + co)*H_ + y)*W_ + c] = v;
        }
    }
}

// ---------------------------------------------------------------------------
// Inputs (metadata order): x, style, noise, weight, style_w, style_b, noise_weight
// ---------------------------------------------------------------------------
extern "C" void kernel_launch(void* const* d_in, const int* in_sizes, int n_in,
                              void* d_out, int out_size) {
    const float* x        = (const float*)d_in[0];
    const float* style    = (const float*)d_in[1];
    const float* noise    = (const float*)d_in[2];
    const float* weight   = (const float*)d_in[3];
    const float* style_w  = (const float*)d_in[4];
    const float* style_b  = (const float*)d_in[5];
    const float* noise_w  = (const float*)d_in[6];
    float* out = (float*)d_out;

    style_kernel<<<N_, STY_>>>(style, style_w, style_b);
    premul_kernel<<<8192, 256>>>(x);
    wsum2_kernel<<<(COUT_*CIN_)/256, 256>>>(weight);
    demod_kernel<<<(N_*COUT_)/256, 256>>>();

    dim3 grid(H_/4, COUT_/64, N_);
    dim3 blk(32, 8);
    conv_kernel<<<grid, blk>>>(weight, noise, noise_w, out);
}

// round 9
// speedup vs baseline: 5.2788x; 5.2788x over previous
#include <cuda_runtime.h>
#include <cstdint>

#define N_    16
#define CIN_  512
#define COUT_ 512
#define STY_  512
#define H_    64
#define W_    64
#define HW_   (H_*W_)
#define QW_   66
#define QTOT_ (QW_*QW_)          /* 4356 padded pixels per image */

// ---------------- static device scratch (no allocation allowed) -------------
__device__ float g_s[N_*CIN_];                       // style modulation
__device__ float g_wsum2[CIN_*COUT_];                // [ci][co] sum_k w^2
__device__ float g_demod[N_*COUT_];                  // demod scale
__device__ float g_wk2[9*CIN_*COUT_];                // [k][ci][co] tf32 weights
__device__ float g_xt2[(size_t)N_*CIN_*QTOT_];       // [n][ci][q] padded, premul, tf32

// ---------------- helpers ---------------------------------------------------
__device__ __forceinline__ uint32_t smem_u32(const void* p) {
    uint32_t a;
    asm("{ .reg .u64 t; cvta.to.shared.u64 t, %1; cvt.u32.u64 %0, t; }"
        : "=r"(a) : "l"(p));
    return a;
}
__device__ __forceinline__ float to_tf32(float v) {
    float r; asm("cvt.rna.tf32.f32 %0, %1;" : "=f"(r) : "f"(v)); return r;
}
__device__ __forceinline__ void cp16(uint32_t dst, const float* src) {
    asm volatile("cp.async.cg.shared.global [%0], [%1], 16;"
                 :: "r"(dst), "l"(src) : "memory");
}
#define CP_COMMIT() asm volatile("cp.async.commit_group;" ::: "memory")
#define CP_WAIT1()  asm volatile("cp.async.wait_group 1;" ::: "memory")

__device__ __forceinline__ void mma_tf32(float* d, const uint32_t* a, const uint32_t* b) {
    asm volatile("mma.sync.aligned.m16n8k8.row.col.f32.tf32.tf32.f32 "
        "{%0,%1,%2,%3}, {%4,%5,%6,%7}, {%8,%9}, {%0,%1,%2,%3};"
        : "+f"(d[0]), "+f"(d[1]), "+f"(d[2]), "+f"(d[3])
        : "r"(a[0]), "r"(a[1]), "r"(a[2]), "r"(a[3]), "r"(b[0]), "r"(b[1]));
}

// ---------------------------------------------------------------------------
// 1) s[n][ci] = style[n] . style_w[ci] + style_b[ci]
// ---------------------------------------------------------------------------
__global__ void style_kernel(const float* __restrict__ style,
                             const float* __restrict__ style_w,
                             const float* __restrict__ style_b) {
    __shared__ float ssty[STY_];
    int n = blockIdx.x;
    int ci = threadIdx.x;
    ssty[ci] = style[n*STY_ + ci];
    __syncthreads();
    const float* wr = style_w + ci*STY_;
    float acc = 0.f;
    #pragma unroll 8
    for (int k = 0; k < STY_; k++) acc += ssty[k] * wr[k];
    g_s[n*CIN_ + ci] = acc + style_b[ci];
}

// ---------------------------------------------------------------------------
// 2) wsum2[ci][co] = sum_k weight[co][ci][k]^2
// ---------------------------------------------------------------------------
__global__ void wsum2_kernel(const float* __restrict__ weight) {
    int idx = blockIdx.x*blockDim.x + threadIdx.x;
    if (idx >= COUT_*CIN_) return;
    int co = idx / CIN_, ci = idx % CIN_;
    const float* w = weight + (size_t)idx*9;
    float a = 0.f;
    #pragma unroll
    for (int k = 0; k < 9; k++) { float v = w[k]; a += v*v; }
    g_wsum2[ci*COUT_ + co] = a;
}

// ---------------------------------------------------------------------------
// 3) demod[n][co] = rsqrt( sum_ci s^2 * wsum2 + eps ) — split-K block reduce
// ---------------------------------------------------------------------------
__global__ void demod_kernel() {
    __shared__ float red[256];
    int n = blockIdx.x, cb = blockIdx.y;
    int co_l = threadIdx.x & 63, g = threadIdx.x >> 6;
    int co = cb*64 + co_l;
    const float* sp = g_s + n*CIN_;
    float acc = 0.f;
    #pragma unroll 16
    for (int ci = g*128; ci < g*128 + 128; ci++) {
        float s = sp[ci];
        acc += s*s*g_wsum2[ci*COUT_ + co];
    }
    red[threadIdx.x] = acc;
    __syncthreads();
    if (g == 0) {
        float t = red[co_l] + red[64+co_l] + red[128+co_l] + red[192+co_l] + 1e-8f;
        g_demod[n*COUT_ + co] = rsqrtf(t);
    }
}

// ---------------------------------------------------------------------------
// 4) weight repack: g_wk2[k][ci][co] = tf32(weight[co][ci][k])  (co contiguous)
// ---------------------------------------------------------------------------
__global__ void pack_w_kernel(const float* __restrict__ w) {
    int f = blockIdx.x*256 + threadIdx.x;
    if (f >= 9*COUT_*CIN_) return;
    int co  = f & (COUT_-1);
    int rem = f >> 9;
    int ci  = rem & (CIN_-1);
    int k   = rem >> 9;
    g_wk2[f] = to_tf32(w[((size_t)co*CIN_ + ci)*9 + k]);
}

// ---------------------------------------------------------------------------
// 5) pack_x: premultiply + tf32 + zero-pad into [n][ci][qy*66+qx]
// ---------------------------------------------------------------------------
__global__ void pack_x_kernel(const float* __restrict__ x) {
    int plane = blockIdx.x;                 // n*CIN + ci
    int q = blockIdx.y*256 + threadIdx.x;
    if (q >= QTOT_) return;
    int qy = q / QW_, qx = q % QW_;
    float v = 0.f;
    if (qy >= 1 && qy <= H_ && qx >= 1 && qx <= W_) {
        float s = g_s[plane];               // plane IS n*512+ci (bug fix)
        v = to_tf32(x[(size_t)plane*HW_ + (qy-1)*W_ + (qx-1)] * s);
    }
    g_xt2[(size_t)plane*QTOT_ + q] = v;
}

// ---------------------------------------------------------------------------
// 6) conv: mma.sync tf32 shifted implicit GEMM + demod + noise + LeakyReLU
//    CTA 128co x 128px (2 rows), 8 warps (2m x 4n), warp tile 64x32.
//    144 iters = 16 ci-chunks x 9 shifts. cp.async double-buffered A & B.
// ---------------------------------------------------------------------------
#define A_STRIDE 136                       /* floats; 136%32==8 -> bank-safe */
#define B_STRIDE 264                       /* floats; 264%32==8 -> bank-safe */
#define A_BYTES  (32*A_STRIDE*4)           /* 17408 */
#define B_BYTES  (32*B_STRIDE*4)           /* 33792 */
#define B_OFF    (2*A_BYTES)               /* 34816 */
#define SMEM_TOTAL (2*A_BYTES + 2*B_BYTES) /* 102400 */

__device__ __forceinline__ void load_A_tile(uint32_t dst, const float* gsrc, int tid) {
    // 32 ci rows x 128 co floats (contiguous per ci, global stride COUT_)
    #pragma unroll
    for (int i = 0; i < 4; i++) {
        int f = tid + i*256;                    // 0..1023
        int ci = f >> 5, co4 = (f & 31) << 2;
        cp16(dst + (uint32_t)(ci*A_STRIDE + co4)*4, gsrc + (size_t)ci*COUT_ + co4);
    }
}
__device__ __forceinline__ void load_B_slab(uint32_t dst, const float* gsrc, int tid) {
    // 32 ci rows x 264 floats (contiguous per ci, global stride QTOT_)
    #pragma unroll
    for (int i = 0; i < 9; i++) {
        int f = tid + i*256;
        if (f < 2112) {
            int ci = f / 66, c4 = (f % 66) << 2;
            cp16(dst + (uint32_t)(ci*B_STRIDE + c4)*4, gsrc + (size_t)ci*QTOT_ + c4);
        }
    }
}

__global__ __launch_bounds__(256, 2)
void conv_mma_kernel(const float* __restrict__ noise,
                     const float* __restrict__ noise_w,
                     float* __restrict__ out) {
    extern __shared__ char smem[];
    const uint32_t sb = smem_u32(smem);
    const int tid  = threadIdx.x;
    const int wid  = tid >> 5;
    const int lane = tid & 31;
    const int g    = lane >> 2;            // groupID
    const int t    = lane & 3;             // threadID_in_group
    const int warp_m = wid & 1;            // 2 m-warps
    const int warp_n = wid >> 1;           // 4 n-warps
    const int co0 = blockIdx.x * 128;
    const int y0  = blockIdx.y * 2;        // 2 output rows per CTA
    const int n   = blockIdx.z;

    const float* wbase = g_wk2 + co0;                                   // +((k*512+ci)*512)
    const float* bbase = g_xt2 + (size_t)n*CIN_*QTOT_ + (size_t)y0*QW_; // +ci*QTOT_

    float acc[4][4][4];
    #pragma unroll
    for (int a = 0; a < 4; a++)
        #pragma unroll
        for (int b = 0; b < 4; b++)
            #pragma unroll
            for (int c = 0; c < 4; c++) acc[a][b][c] = 0.f;

    // prologue: prefetch B slab(chunk 0) + A tile(j=0)
    load_B_slab(sb + B_OFF, bbase, tid);
    load_A_tile(sb, wbase, tid);
    CP_COMMIT();

    int chunk = 0, k9 = 0;
    for (int j = 0; j < 144; j++) {
        // ---- prefetch data for j+1 into alternate buffers ----
        int nk9 = k9 + 1, nchunk = chunk;
        if (nk9 == 9) { nk9 = 0; nchunk++; }
        if (j < 143)
            load_A_tile(sb + ((j+1)&1)*A_BYTES,
                        wbase + ((size_t)(nk9*CIN_) + (size_t)nchunk*32)*COUT_, tid);
        if (k9 == 0 && chunk + 1 < 16)
            load_B_slab(sb + B_OFF + ((chunk+1)&1)*B_BYTES,
                        bbase + (size_t)(chunk+1)*32*QTOT_, tid);
        CP_COMMIT();
        CP_WAIT1();                        // group for data(j) complete
        __syncthreads();

        const float* As = (const float*)(smem + (j&1)*A_BYTES);
        const float* Bs = (const float*)(smem + B_OFF + (chunk&1)*B_BYTES);
        const int kh = k9 / 3, kw = k9 % 3;
        const float* Bsh = Bs + kh*QW_ + kw;

        #pragma unroll
        for (int ks = 0; ks < 4; ks++) {
            uint32_t af[4][4], bf[4][2];
            const float* ak = As + (ks*8 + t)*A_STRIDE + warp_m*64 + g;
            #pragma unroll
            for (int mt = 0; mt < 4; mt++) {
                const float* ap = ak + mt*16;
                af[mt][0] = __float_as_uint(ap[0]);                 // (g,   t)
                af[mt][1] = __float_as_uint(ap[8]);                 // (g+8, t)
                af[mt][2] = __float_as_uint(ap[4*A_STRIDE]);        // (g,   t+4)
                af[mt][3] = __float_as_uint(ap[4*A_STRIDE + 8]);    // (g+8, t+4)
            }
            const float* bk = Bsh + (ks*8 + t)*B_STRIDE;
            #pragma unroll
            for (int nt = 0; nt < 4; nt++) {
                int px0 = warp_n*32 + nt*8;
                int off = (px0 >> 6)*QW_ + (px0 & 63) + g;
                bf[nt][0] = __float_as_uint(bk[off]);               // (t,   g)
                bf[nt][1] = __float_as_uint(bk[off + 4*B_STRIDE]);  // (t+4, g)
            }
            #pragma unroll
            for (int mt = 0; mt < 4; mt++)
                #pragma unroll
                for (int nt = 0; nt < 4; nt++)
                    mma_tf32(acc[mt][nt], af[mt], bf[nt]);
        }
        __syncthreads();                   // before next iter overwrites buffers

        k9 = nk9; chunk = nchunk;
    }

    // ---- epilogue: demod, noise, LeakyReLU(0.2) ----
    const float nw = noise_w[0];
    #pragma unroll
    for (int mt = 0; mt < 4; mt++) {
        int co_a = co0 + warp_m*64 + mt*16 + g;
        float dm0 = g_demod[n*COUT_ + co_a];
        float dm1 = g_demod[n*COUT_ + co_a + 8];
        float* o0 = out + ((size_t)n*COUT_ + co_a)*HW_ + (size_t)y0*W_;
        float* o1 = o0 + (size_t)8*HW_;
        #pragma unroll
        for (int nt = 0; nt < 4; nt++) {
            int px0 = warp_n*32 + nt*8;
            int r = px0 >> 6;
            int c = (px0 & 63) + 2*t;
            const float* np = noise + ((size_t)n*H_ + y0 + r)*W_ + c;
            float n0 = np[0], n1 = np[1];
            float v0 = acc[mt][nt][0]*dm0 + nw*n0; v0 = fmaxf(v0, 0.2f*v0);
            float v1 = acc[mt][nt][1]*dm0 + nw*n1; v1 = fmaxf(v1, 0.2f*v1);
            float v2 = acc[mt][nt][2]*dm1 + nw*n0; v2 = fmaxf(v2, 0.2f*v2);
            float v3 = acc[mt][nt][3]*dm1 + nw*n1; v3 = fmaxf(v3, 0.2f*v3);
            *(float2*)(o0 + (size_t)r*W_ + c) = make_float2(v0, v1);
            *(float2*)(o1 + (size_t)r*W_ + c) = make_float2(v2, v3);
        }
    }
}

// ---------------------------------------------------------------------------
// Inputs: x, style, noise, weight, style_w, style_b, noise_weight
// ---------------------------------------------------------------------------
extern "C" void kernel_launch(void* const* d_in, const int* in_sizes, int n_in,
                              void* d_out, int out_size) {
    const float* x        = (const float*)d_in[0];
    const float* style    = (const float*)d_in[1];
    const float* noise    = (const float*)d_in[2];
    const float* weight   = (const float*)d_in[3];
    const float* style_w  = (const float*)d_in[4];
    const float* style_b  = (const float*)d_in[5];
    const float* noise_w  = (const float*)d_in[6];
    float* out = (float*)d_out;

    style_kernel<<<N_, STY_>>>(style, style_w, style_b);
    wsum2_kernel<<<(COUT_*CIN_)/256, 256>>>(weight);
    demod_kernel<<<dim3(N_, COUT_/64), 256>>>();
    pack_w_kernel<<<(9*COUT_*CIN_ + 255)/256, 256>>>(weight);
    pack_x_kernel<<<dim3(N_*CIN_, (QTOT_+255)/256), 256>>>(x);

    cudaFuncSetAttribute(conv_mma_kernel,
                         cudaFuncAttributeMaxDynamicSharedMemorySize, SMEM_TOTAL);
    conv_mma_kernel<<<dim3(COUT_/128, H_/2, N_), 256, SMEM_TOTAL>>>(noise, noise_w, out);
}